// round 7
// baseline (speedup 1.0000x reference)
#include <cuda_runtime.h>
#include <math.h>

#define NRES 10000
#define KNN 30
#define HDIM 32
#define EFD 32
#define NEDGE (NRES*KNN)

// ---------------- device scratch ----------------
__device__ float g_h0[2][NRES*HDIM];
__device__ float g_h1[2][NRES*3*HDIM];
__device__ float g_ef[NEDGE*EFD];
__device__ int   g_src[NEDGE];
__device__ float4 g_xca4[NRES];
__device__ int   g_bstart[8];
__device__ int   g_bend[8];
// double-buffered per-node precomputes (slot = layer & 1)
__device__ float g_hs2[2][NRES*HDIM];
__device__ float g_hd2[2][NRES*HDIM];
__device__ float g_hv2[2][NRES*3*HDIM];
__device__ float g_ps2[2][NRES*64];
__device__ float g_pd2[2][NRES*64];

__constant__ int c_aa[87] = {
  0,
  1,1,1,1,1,1,1, 2,2,2,2, 3,3,3,3, 4,4, 5,5,5,5,5, 6,6,6,6,6,
  8,8,8,8,8,8, 9,9,9,9, 10,10,10,10, 11,11,11,11,11, 12,12,12,12,
  13,13,13,13,13,13,13, 14,14,14, 15,15, 16,16,16,
  17,17,17,17,17,17,17,17,17,17, 18,18,18,18,18,18,18,18, 19,19,19
};
__constant__ int c_off[87] = {
  0,
  0,1,2,3,4,5,6, 0,1,2,3, 0,1,2,3, 0,1, 0,1,2,3,4, 0,1,2,3,4,
  0,1,2,3,4,5, 0,1,2,3, 0,1,2,3, 0,1,2,3,4, 0,1,2,3,
  0,1,2,3,4,5,6, 0,1,2, 0,1, 0,1,2,
  0,1,2,3,4,5,6,7,8,9, 0,1,2,3,4,5,6,7, 0,1,2
};

__device__ __forceinline__ float fin0(float v){ return isfinite(v) ? v : 0.f; }

// ---------------- batch ranges ----------------
__global__ void init_ranges_kernel(){
  int t = threadIdx.x;
  if (t < 8){ g_bstart[t] = NRES; g_bend[t] = 0; }
}
__global__ void batch_range_kernel(const int* __restrict__ bid){
  int i = blockIdx.x*blockDim.x + threadIdx.x;
  if (i >= NRES) return;
  int b = bid[i];
  atomicMin(&g_bstart[b], i);
  atomicMax(&g_bend[b], i+1);
}

// ---------------- node features + embeddings + layer-0 precompute ----------------
__global__ __launch_bounds__(256) void node_embed_kernel(
    const float* __restrict__ bb, const float* __restrict__ lat,
    const float* __restrict__ Wemb0, const float* __restrict__ Wemb1,
    const float* __restrict__ Wss0, const float* __restrict__ Wds0,
    const float* __restrict__ Wvs0)
{
  int lane = threadIdx.x & 31;
  int i = blockIdx.x*8 + (threadIdx.x >> 5);
  if (i >= NRES) return;

  float ca0 = bb[i*12+3], ca1 = bb[i*12+4], ca2 = bb[i*12+5];
  if (lane == 0){
    g_xca4[i] = make_float4(ca0, ca1, ca2, ca0*ca0 + ca1*ca1 + ca2*ca2);
  }

  float Dv[3];
  #pragma unroll
  for (int t3 = 0; t3 < 3; t3++){
    int t = 3*i + t3;
    float D = 0.f;
    if (t >= 1 && t <= 3*NRES - 3){
      int d0 = t - 1;
      float x[4][3];
      #pragma unroll
      for (int q = 0; q < 4; q++){
        int m = d0 + q; int r = m/3; int am = m - r*3;
        x[q][0] = bb[r*12 + am*3 + 0];
        x[q][1] = bb[r*12 + am*3 + 1];
        x[q][2] = bb[r*12 + am*3 + 2];
      }
      float u2[3], u1[3], u0[3];
      #pragma unroll
      for (int c = 0; c < 3; c++){ u2[c]=x[1][c]-x[0][c]; u1[c]=x[2][c]-x[1][c]; u0[c]=x[3][c]-x[2][c]; }
      float n2n = sqrtf(u2[0]*u2[0]+u2[1]*u2[1]+u2[2]*u2[2]) + 1e-8f;
      float n1n = sqrtf(u1[0]*u1[0]+u1[1]*u1[1]+u1[2]*u1[2]) + 1e-8f;
      float n0n = sqrtf(u0[0]*u0[0]+u0[1]*u0[1]+u0[2]*u0[2]) + 1e-8f;
      #pragma unroll
      for (int c = 0; c < 3; c++){ u2[c]/=n2n; u1[c]/=n1n; u0[c]/=n0n; }
      float c21[3] = { u2[1]*u1[2]-u2[2]*u1[1], u2[2]*u1[0]-u2[0]*u1[2], u2[0]*u1[1]-u2[1]*u1[0] };
      float c10[3] = { u1[1]*u0[2]-u1[2]*u0[1], u1[2]*u0[0]-u1[0]*u0[2], u1[0]*u0[1]-u1[1]*u0[0] };
      float l21 = sqrtf(c21[0]*c21[0]+c21[1]*c21[1]+c21[2]*c21[2]) + 1e-8f;
      float l10 = sqrtf(c10[0]*c10[0]+c10[1]*c10[1]+c10[2]*c10[2]) + 1e-8f;
      #pragma unroll
      for (int c = 0; c < 3; c++){ c21[c]/=l21; c10[c]/=l10; }
      float cosD = c21[0]*c10[0]+c21[1]*c10[1]+c21[2]*c10[2];
      cosD = fminf(fmaxf(cosD, -1.f + 1e-7f), 1.f - 1e-7f);
      float sdot = u2[0]*c10[0]+u2[1]*c10[1]+u2[2]*c10[2];
      float sgn = (sdot > 0.f) ? 1.f : ((sdot < 0.f) ? -1.f : 0.f);
      D = sgn * acosf(cosD);
    }
    Dv[t3] = D;
  }
  float x0[7] = { cosf(Dv[0]), cosf(Dv[1]), cosf(Dv[2]),
                  sinf(Dv[0]), sinf(Dv[1]), sinf(Dv[2]), 1.f };

  float v[7][3];
  #pragma unroll
  for (int a = 0; a < 4; a++){
    v[a][0] = bb[i*12 + a*3 + 0] - ca0;
    v[a][1] = bb[i*12 + a*3 + 1] - ca1;
    v[a][2] = bb[i*12 + a*3 + 2] - ca2;
  }
  if (i < NRES-1){
    float dx = bb[(i+1)*12+3] - ca0, dy = bb[(i+1)*12+4] - ca1, dz = bb[(i+1)*12+5] - ca2;
    float n = sqrtf(dx*dx+dy*dy+dz*dz) + 1e-8f;
    v[4][0]=dx/n; v[4][1]=dy/n; v[4][2]=dz/n;
  } else { v[4][0]=v[4][1]=v[4][2]=0.f; }
  if (i > 0){
    float dx = ca0 - bb[(i-1)*12+3], dy = ca1 - bb[(i-1)*12+4], dz = ca2 - bb[(i-1)*12+5];
    float n = sqrtf(dx*dx+dy*dy+dz*dz) + 1e-8f;
    v[5][0]=-dx/n; v[5][1]=-dy/n; v[5][2]=-dz/n;
  } else { v[5][0]=v[5][1]=v[5][2]=0.f; }
  {
    float b0 = ca0 - bb[i*12+0], b1 = ca1 - bb[i*12+1], b2 = ca2 - bb[i*12+2];
    float cc0 = bb[i*12+6] - ca0, cc1 = bb[i*12+7] - ca1, cc2 = bb[i*12+8] - ca2;
    float a0 = b1*cc2 - b2*cc1, a1 = b2*cc0 - b0*cc2, a2 = b0*cc1 - b1*cc0;
    v[6][0] = -0.58273431f*a0 + 0.56802827f*b0 - 0.54067466f*cc0;
    v[6][1] = -0.58273431f*a1 + 0.56802827f*b1 - 0.54067466f*cc1;
    v[6][2] = -0.58273431f*a2 + 0.56802827f*b2 - 0.54067466f*cc2;
  }
  #pragma unroll
  for (int q = 0; q < 7; q++){
    v[q][0]=fin0(v[q][0]); v[q][1]=fin0(v[q][1]); v[q][2]=fin0(v[q][2]);
  }

  float acc = 0.f;
  #pragma unroll
  for (int d = 0; d < 7; d++) acc = fmaf(x0[d], Wemb0[d*32 + lane], acc);
  for (int d = 0; d < 32; d++) acc = fmaf(lat[(i*4+0)*32 + d], Wemb0[(7+d)*32 + lane], acc);
  float h0r = fmaxf(acc, 0.f);
  g_h0[0][i*32 + lane] = h0r;

  float h1r[3];
  #pragma unroll
  for (int j = 0; j < 3; j++){
    float a2 = 0.f;
    #pragma unroll
    for (int d = 0; d < 7; d++) a2 = fmaf(v[d][j], Wemb1[d*32 + lane], a2);
    for (int d = 0; d < 32; d++) a2 = fmaf(lat[(i*4+1+j)*32 + d], Wemb1[(7+d)*32 + lane], a2);
    h1r[j] = a2;
    g_h1[0][(i*3+j)*32 + lane] = a2;
  }

  // layer-0 precompute: hs0 = h0 @ Wss0, hd0 = h0 @ Wds0, hv0 = h1 @ Wvs0 -> slot 0
  float hs = 0.f, hdv = 0.f;
  #pragma unroll
  for (int d = 0; d < 32; d++){
    float a = __shfl_sync(0xffffffffu, h0r, d);
    hs  = fmaf(a, __ldg(&Wss0[d*32+lane]), hs);
    hdv = fmaf(a, __ldg(&Wds0[d*32+lane]), hdv);
  }
  g_hs2[0][i*32+lane] = hs;
  g_hd2[0][i*32+lane] = hdv;
  #pragma unroll
  for (int c = 0; c < 3; c++){
    float hv = 0.f;
    #pragma unroll
    for (int d = 0; d < 32; d++)
      hv = fmaf(__shfl_sync(0xffffffffu, h1r[c], d), __ldg(&Wvs0[d*32+lane]), hv);
    g_hv2[0][i*96 + c*32 + lane] = hv;
  }
}

// ---------------- kNN: one WARP per row, register-only bitonic top-32 ----------------
__device__ __forceinline__ unsigned long long shfx64(unsigned long long v, int m){
  return __shfl_xor_sync(0xffffffffu, v, m);
}

__global__ __launch_bounds__(256) void knn_kernel(const int* __restrict__ bid){
  int lane = threadIdx.x & 31;
  int i = blockIdx.x*8 + (threadIdx.x >> 5);
  if (i >= NRES) return;
  float4 qi = g_xca4[i];
  int b = bid[i];
  int lo = g_bstart[b], hi = g_bend[b];

  const unsigned long long INF = 0xFFFFFFFFFFFFFFFFull;
  unsigned long long state = INF;
  unsigned long long worst = INF;

  for (int j0 = lo; j0 < hi; j0 += 32){
    int j = j0 + lane;
    unsigned long long key = INF;
    if (j < hi && j != i){
      float4 qj = g_xca4[j];
      float d2 = fmaf(-2.f, qi.x*qj.x + qi.y*qj.y + qi.z*qj.z, qi.w + qj.w);
      unsigned int fb = __float_as_uint(d2);
      fb = (fb & 0x80000000u) ? ~fb : (fb | 0x80000000u);
      key = ((unsigned long long)fb << 32) | (unsigned int)j;
    }
    if (!__any_sync(0xffffffffu, key < worst)) continue;

    #pragma unroll
    for (int k = 2; k <= 32; k <<= 1){
      #pragma unroll
      for (int jj = k >> 1; jj > 0; jj >>= 1){
        unsigned long long o = shfx64(key, jj);
        bool up = ((lane & k) == 0);
        bool lower = ((lane & jj) == 0);
        bool keepmin = (up == lower);
        key = ((o < key) == keepmin) ? o : key;
      }
    }
    unsigned long long rev = shfx64(key, 31);
    unsigned long long m = (rev < state) ? rev : state;
    #pragma unroll
    for (int jj = 16; jj > 0; jj >>= 1){
      unsigned long long o = shfx64(m, jj);
      bool lower = ((lane & jj) == 0);
      m = ((o < m) == lower) ? o : m;
    }
    state = m;
    worst = __shfl_sync(0xffffffffu, state, 31);
  }

  if (lane < KNN){
    g_src[i*KNN + lane] = (state == INF) ? i : (int)(unsigned int)(state & 0xFFFFFFFFull);
  }
}

// ---------------- edge init ----------------
__global__ void edge_init_kernel(){
  int e = blockIdx.x*blockDim.x + threadIdx.x;
  if (e >= NEDGE) return;
  int i = e / KNN;
  int s = g_src[e];
  float4 qi = g_xca4[i], qs = g_xca4[s];
  float vx = qi.x - qs.x, vy = qi.y - qs.y, vz = qi.z - qs.z;
  float dist = sqrtf(vx*vx + vy*vy + vz*vz);
  float* ef = &g_ef[e*EFD];
  #pragma unroll
  for (int j = 0; j < 16; j++){
    float mu = (float)j * (20.f/15.f);
    float t = (dist - mu) / 1.25f;
    ef[j] = expf(-t*t);
  }
  float diff = (float)(s - i);
  #pragma unroll
  for (int f = 0; f < 8; f++){
    float fr = expf(-((float)(2*f)/16.f) * 9.210340371976184f);
    float a = diff * fr;
    ef[16+f] = cosf(a);
    ef[24+f] = sinf(a);
  }
}

// ---------------- F0: phase1(layer 0) + epilogue [ps0/pd0 -> slot0, hs1/hd1/hv1 -> slot1] ----------------
#define CHK 10
__global__ __launch_bounds__(256) void mp_first(
    const float* __restrict__ We1, const float* __restrict__ We2,
    const float* __restrict__ W0,  const float* __restrict__ W1,
    const float* __restrict__ Wu1,
    const float* __restrict__ Wss1, const float* __restrict__ Wds1,
    const float* __restrict__ Wvs1)
{
  __shared__ __align__(16) float sWe1T[1024];
  __shared__ __align__(16) float sWe2T[1024];
  __shared__ __align__(16) float sE[8][CHK][32];
  __shared__ __align__(16) float sT[8][CHK][32];
  __shared__ int sSrc[8][32];

  for (int t = threadIdx.x; t < 1024; t += 256){
    sWe1T[t] = We1[(t&31)*32 + (t>>5)];
    sWe2T[t] = We2[(t&31)*32 + (t>>5)];
  }
  __syncthreads();

  const float* h0in = g_h0[0];  float* h0out = g_h0[1];
  const float* h1in = g_h1[0];  float* h1out = g_h1[1];
  int lane = threadIdx.x & 31;
  int w = threadIdx.x >> 5;
  int i = blockIdx.x*8 + w;
  if (i >= NRES) return;

  if (lane < KNN) sSrc[w][lane] = g_src[i*KNN + lane];
  __syncwarp();

  float h0d = h0in[i*HDIM + lane];
  float hd  = g_hd2[0][i*HDIM + lane];
  float acc0 = 0.f, av0 = 0.f, av1 = 0.f, av2 = 0.f;

  for (int c0 = 0; c0 < KNN; c0 += CHK){
    #pragma unroll
    for (int k = 0; k < CHK; k++)
      sE[w][k][lane] = g_ef[((size_t)(i*KNN + c0 + k))*EFD + lane];
    __syncwarp();
    #pragma unroll
    for (int k = 0; k < CHK; k++){
      int s = sSrc[w][c0 + k];
      float t0 = hd + g_hs2[0][s*HDIM + lane];
      float t1 = 0.f;
      #pragma unroll
      for (int d4 = 0; d4 < 8; d4++){
        float4 a  = *(const float4*)&sE[w][k][d4*4];
        float4 wv = *(const float4*)&sWe1T[lane*32 + d4*4];
        t0 = fmaf(a.x, wv.x, t0); t1 = fmaf(a.y, wv.y, t1);
        t0 = fmaf(a.z, wv.z, t0); t1 = fmaf(a.w, wv.w, t1);
      }
      sT[w][k][lane] = fmaxf(t0 + t1, 0.f);
    }
    __syncwarp();
    #pragma unroll
    for (int k = 0; k < CHK; k++){
      int s = sSrc[w][c0 + k];
      float g0 = 0.f, g1 = 0.f;
      #pragma unroll
      for (int d4 = 0; d4 < 8; d4++){
        float4 a  = *(const float4*)&sT[w][k][d4*4];
        float4 wv = *(const float4*)&sWe2T[lane*32 + d4*4];
        g0 = fmaf(a.x, wv.x, g0); g1 = fmaf(a.y, wv.y, g1);
        g0 = fmaf(a.z, wv.z, g0); g1 = fmaf(a.w, wv.w, g1);
      }
      float g = g0 + g1;
      acc0 = fmaf(g, h0in[s*HDIM + lane], acc0);
      const float* hv = &g_hv2[0][s*96];
      av0 = fmaf(g, hv[lane],    av0);
      av1 = fmaf(g, hv[32+lane], av1);
      av2 = fmaf(g, hv[64+lane], av2);
    }
    __syncwarp();
  }

  const float inv = 1.f/(float)KNN;
  acc0 *= inv; av0 *= inv; av1 *= inv; av2 *= inv;

  float u0 = 0.f, u1 = 0.f;
  #pragma unroll
  for (int d = 0; d < 32; d += 2){
    u0 = fmaf(__shfl_sync(0xffffffffu, acc0, d),   __ldg(&W0[d*32+lane]),     u0);
    u1 = fmaf(__shfl_sync(0xffffffffu, acc0, d+1), __ldg(&W0[(d+1)*32+lane]), u1);
  }
  float h0new = h0d + fmaxf(u0 + u1, 0.f);
  h0out[i*HDIM + lane] = h0new;

  float o0 = 0.f, o1 = 0.f, o2 = 0.f;
  #pragma unroll
  for (int d = 0; d < 32; d++){
    float wv = __ldg(&W1[d*32+lane]);
    o0 = fmaf(__shfl_sync(0xffffffffu, av0, d), wv, o0);
    o1 = fmaf(__shfl_sync(0xffffffffu, av1, d), wv, o1);
    o2 = fmaf(__shfl_sync(0xffffffffu, av2, d), wv, o2);
  }
  float h1n0 = h1in[(i*3+0)*HDIM + lane] + o0;
  float h1n1 = h1in[(i*3+1)*HDIM + lane] + o1;
  float h1n2 = h1in[(i*3+2)*HDIM + lane] + o2;
  h1out[(i*3+0)*HDIM + lane] = h1n0;
  h1out[(i*3+1)*HDIM + lane] = h1n1;
  h1out[(i*3+2)*HDIM + lane] = h1n2;

  // ps0/pd0 (slot 0) from h0new
  const float* U1b = Wu1 + 2048;
  const float* U1c = Wu1 + 4096;
  float psa = 0.f, psb = 0.f, pda = 0.f, pdb = 0.f;
  #pragma unroll
  for (int d = 0; d < 32; d++){
    float h = __shfl_sync(0xffffffffu, h0new, d);
    psa = fmaf(h, __ldg(&U1b[d*64 + lane]),      psa);
    psb = fmaf(h, __ldg(&U1b[d*64 + 32 + lane]), psb);
    pda = fmaf(h, __ldg(&U1c[d*64 + lane]),      pda);
    pdb = fmaf(h, __ldg(&U1c[d*64 + 32 + lane]), pdb);
  }
  g_ps2[0][i*64 + lane]      = psa;
  g_ps2[0][i*64 + 32 + lane] = psb;
  g_pd2[0][i*64 + lane]      = pda;
  g_pd2[0][i*64 + 32 + lane] = pdb;

  // hs1/hd1 (slot 1) from h0new, hv1 (slot 1) from h1new
  float hs = 0.f, hdv = 0.f;
  #pragma unroll
  for (int d = 0; d < 32; d++){
    float a = __shfl_sync(0xffffffffu, h0new, d);
    hs  = fmaf(a, __ldg(&Wss1[d*32+lane]), hs);
    hdv = fmaf(a, __ldg(&Wds1[d*32+lane]), hdv);
  }
  g_hs2[1][i*32+lane] = hs;
  g_hd2[1][i*32+lane] = hdv;
  float hvv0 = 0.f, hvv1 = 0.f, hvv2 = 0.f;
  #pragma unroll
  for (int d = 0; d < 32; d++){
    float wv = __ldg(&Wvs1[d*32+lane]);
    hvv0 = fmaf(__shfl_sync(0xffffffffu, h1n0, d), wv, hvv0);
    hvv1 = fmaf(__shfl_sync(0xffffffffu, h1n1, d), wv, hvv1);
    hvv2 = fmaf(__shfl_sync(0xffffffffu, h1n2, d), wv, hvv2);
  }
  g_hv2[1][i*96 + lane]      = hvv0;
  g_hv2[1][i*96 + 32 + lane] = hvv1;
  g_hv2[1][i*96 + 64 + lane] = hvv2;
}

// ---------------- G: fused phase2(l) + phase1(l+1) + epilogue ----------------
// slotL = l&1. Reads: ps/pd slot slotL, hs/hd/hv slot slotL^1, h0/h1 buffer bufIn.
// Writes: h0/h1 buffer bufIn^1; ps/pd(l+1) -> slot slotL^1; hs/hd/hv(l+2) -> slot slotL.
#define GCHK 6
template<bool LAST>
__global__ __launch_bounds__(256) void mp_fused(
    int bufIn, int slotL,
    const float* __restrict__ Wu1a, const float* __restrict__ Wu2,
    const float* __restrict__ We1n, const float* __restrict__ We2n,
    const float* __restrict__ W0n,  const float* __restrict__ W1n,
    const float* __restrict__ Wu1n,
    const float* __restrict__ Wssnn, const float* __restrict__ Wdsnn,
    const float* __restrict__ Wvsnn)
{
  __shared__ __align__(16) float sU1aT[2048];  // [c 0..63][d 0..31]
  __shared__ __align__(16) float sW2T[2048];   // [c 0..31][h 0..63]
  __shared__ __align__(16) float sWe1T[1024];  // [c][d]
  __shared__ __align__(16) float sWe2T[1024];  // [c][d]
  __shared__ __align__(16) float sE[8][GCHK][32];
  __shared__ __align__(16) float sTY[8][GCHK][64];
  __shared__ int sSrc[8][32];

  for (int t = threadIdx.x; t < 2048; t += 256){
    sU1aT[t] = Wu1a[(t&31)*64 + (t>>5)];
    sW2T[t]  = Wu2[(t&63)*32 + (t>>6)];
  }
  for (int t = threadIdx.x; t < 1024; t += 256){
    sWe1T[t] = We1n[(t&31)*32 + (t>>5)];
    sWe2T[t] = We2n[(t&31)*32 + (t>>5)];
  }
  __syncthreads();

  int lane = threadIdx.x & 31;
  int w = threadIdx.x >> 5;
  int i = blockIdx.x*8 + w;
  if (i >= NRES) return;
  int slotN = slotL ^ 1;

  if (lane < KNN) sSrc[w][lane] = g_src[i*KNN + lane];
  __syncwarp();

  const float* h0in = g_h0[bufIn];  float* h0out = g_h0[bufIn^1];
  const float* h1in = g_h1[bufIn];  float* h1out = g_h1[bufIn^1];
  const float* psL = g_ps2[slotL];
  const float* hsN = g_hs2[slotN];
  const float* hvN = g_hv2[slotN];

  float h0d = h0in[i*HDIM + lane];
  float hd  = g_hd2[slotN][i*HDIM + lane];
  float pda = g_pd2[slotL][i*64 + lane];
  float pdb = g_pd2[slotL][i*64 + 32 + lane];
  float acc0 = 0.f, av0 = 0.f, av1 = 0.f, av2 = 0.f;

  for (int c0 = 0; c0 < KNN; c0 += GCHK){
    #pragma unroll
    for (int k = 0; k < GCHK; k++)
      sE[w][k][lane] = g_ef[((size_t)(i*KNN + c0 + k))*EFD + lane];
    __syncwarp();
    // phase2 A: y = relu(pd + ps[s] + ef @ U1a)
    #pragma unroll
    for (int k = 0; k < GCHK; k++){
      int s = sSrc[w][c0 + k];
      float y0 = pda + psL[s*64 + lane];
      float y1 = pdb + psL[s*64 + 32 + lane];
      #pragma unroll
      for (int d4 = 0; d4 < 8; d4++){
        float4 a  = *(const float4*)&sE[w][k][d4*4];
        float4 w0 = *(const float4*)&sU1aT[lane*32 + d4*4];
        float4 w1 = *(const float4*)&sU1aT[(lane+32)*32 + d4*4];
        y0 = fmaf(a.x, w0.x, y0); y0 = fmaf(a.y, w0.y, y0);
        y0 = fmaf(a.z, w0.z, y0); y0 = fmaf(a.w, w0.w, y0);
        y1 = fmaf(a.x, w1.x, y1); y1 = fmaf(a.y, w1.y, y1);
        y1 = fmaf(a.z, w1.z, y1); y1 = fmaf(a.w, w1.w, y1);
      }
      sTY[w][k][lane]      = fmaxf(y0, 0.f);
      sTY[w][k][32 + lane] = fmaxf(y1, 0.f);
    }
    __syncwarp();
    // phase2 B: ef_new = ef + y @ Wu2  (kept in sE; written back unless LAST)
    #pragma unroll
    for (int k = 0; k < GCHK; k++){
      float oA = 0.f, oB = 0.f;
      #pragma unroll
      for (int h4 = 0; h4 < 16; h4++){
        float4 a  = *(const float4*)&sTY[w][k][h4*4];
        float4 wv = *(const float4*)&sW2T[lane*64 + h4*4];
        oA = fmaf(a.x, wv.x, oA); oB = fmaf(a.y, wv.y, oB);
        oA = fmaf(a.z, wv.z, oA); oB = fmaf(a.w, wv.w, oB);
      }
      float efn = sE[w][k][lane] + oA + oB;
      sE[w][k][lane] = efn;
      if (!LAST) g_ef[((size_t)(i*KNN + c0 + k))*EFD + lane] = efn;
    }
    __syncwarp();
    // phase1 A: t = relu(hd + hs[s] + ef_new @ We1)
    #pragma unroll
    for (int k = 0; k < GCHK; k++){
      int s = sSrc[w][c0 + k];
      float t0 = hd + hsN[s*HDIM + lane];
      float t1 = 0.f;
      #pragma unroll
      for (int d4 = 0; d4 < 8; d4++){
        float4 a  = *(const float4*)&sE[w][k][d4*4];
        float4 wv = *(const float4*)&sWe1T[lane*32 + d4*4];
        t0 = fmaf(a.x, wv.x, t0); t1 = fmaf(a.y, wv.y, t1);
        t0 = fmaf(a.z, wv.z, t0); t1 = fmaf(a.w, wv.w, t1);
      }
      sTY[w][k][lane] = fmaxf(t0 + t1, 0.f);
    }
    __syncwarp();
    // phase1 B: g = t @ We2; accumulate
    #pragma unroll
    for (int k = 0; k < GCHK; k++){
      int s = sSrc[w][c0 + k];
      float g0 = 0.f, g1 = 0.f;
      #pragma unroll
      for (int d4 = 0; d4 < 8; d4++){
        float4 a  = *(const float4*)&sTY[w][k][d4*4];
        float4 wv = *(const float4*)&sWe2T[lane*32 + d4*4];
        g0 = fmaf(a.x, wv.x, g0); g1 = fmaf(a.y, wv.y, g1);
        g0 = fmaf(a.z, wv.z, g0); g1 = fmaf(a.w, wv.w, g1);
      }
      float g = g0 + g1;
      acc0 = fmaf(g, h0in[s*HDIM + lane], acc0);
      if (!LAST){
        const float* hv = &hvN[s*96];
        av0 = fmaf(g, hv[lane],    av0);
        av1 = fmaf(g, hv[32+lane], av1);
        av2 = fmaf(g, hv[64+lane], av2);
      }
    }
    __syncwarp();
  }

  const float inv = 1.f/(float)KNN;
  acc0 *= inv;

  float u0 = 0.f, u1 = 0.f;
  #pragma unroll
  for (int d = 0; d < 32; d += 2){
    u0 = fmaf(__shfl_sync(0xffffffffu, acc0, d),   __ldg(&W0n[d*32+lane]),     u0);
    u1 = fmaf(__shfl_sync(0xffffffffu, acc0, d+1), __ldg(&W0n[(d+1)*32+lane]), u1);
  }
  float h0new = h0d + fmaxf(u0 + u1, 0.f);
  h0out[i*HDIM + lane] = h0new;

  if (!LAST){
    av0 *= inv; av1 *= inv; av2 *= inv;
    float o0 = 0.f, o1 = 0.f, o2 = 0.f;
    #pragma unroll
    for (int d = 0; d < 32; d++){
      float wv = __ldg(&W1n[d*32+lane]);
      o0 = fmaf(__shfl_sync(0xffffffffu, av0, d), wv, o0);
      o1 = fmaf(__shfl_sync(0xffffffffu, av1, d), wv, o1);
      o2 = fmaf(__shfl_sync(0xffffffffu, av2, d), wv, o2);
    }
    float h1n0 = h1in[(i*3+0)*HDIM + lane] + o0;
    float h1n1 = h1in[(i*3+1)*HDIM + lane] + o1;
    float h1n2 = h1in[(i*3+2)*HDIM + lane] + o2;
    h1out[(i*3+0)*HDIM + lane] = h1n0;
    h1out[(i*3+1)*HDIM + lane] = h1n1;
    h1out[(i*3+2)*HDIM + lane] = h1n2;

    // ps/pd(l+1) -> slotN
    const float* U1b = Wu1n + 2048;
    const float* U1c = Wu1n + 4096;
    float psa = 0.f, psb = 0.f, pda2 = 0.f, pdb2 = 0.f;
    #pragma unroll
    for (int d = 0; d < 32; d++){
      float h = __shfl_sync(0xffffffffu, h0new, d);
      psa  = fmaf(h, __ldg(&U1b[d*64 + lane]),      psa);
      psb  = fmaf(h, __ldg(&U1b[d*64 + 32 + lane]), psb);
      pda2 = fmaf(h, __ldg(&U1c[d*64 + lane]),      pda2);
      pdb2 = fmaf(h, __ldg(&U1c[d*64 + 32 + lane]), pdb2);
    }
    g_ps2[slotN][i*64 + lane]      = psa;
    g_ps2[slotN][i*64 + 32 + lane] = psb;
    g_pd2[slotN][i*64 + lane]      = pda2;
    g_pd2[slotN][i*64 + 32 + lane] = pdb2;

    // hs/hd(l+2) -> slotL from h0new; hv(l+2) -> slotL from h1new
    float hs = 0.f, hdv = 0.f;
    #pragma unroll
    for (int d = 0; d < 32; d++){
      float a = __shfl_sync(0xffffffffu, h0new, d);
      hs  = fmaf(a, __ldg(&Wssnn[d*32+lane]), hs);
      hdv = fmaf(a, __ldg(&Wdsnn[d*32+lane]), hdv);
    }
    g_hs2[slotL][i*32+lane] = hs;
    g_hd2[slotL][i*32+lane] = hdv;
    float hvv0 = 0.f, hvv1 = 0.f, hvv2 = 0.f;
    #pragma unroll
    for (int d = 0; d < 32; d++){
      float wv = __ldg(&Wvsnn[d*32+lane]);
      hvv0 = fmaf(__shfl_sync(0xffffffffu, h1n0, d), wv, hvv0);
      hvv1 = fmaf(__shfl_sync(0xffffffffu, h1n1, d), wv, hvv1);
      hvv2 = fmaf(__shfl_sync(0xffffffffu, h1n2, d), wv, hvv2);
    }
    g_hv2[slotL][i*96 + lane]      = hvv0;
    g_hv2[slotL][i*96 + 32 + lane] = hvv1;
    g_hv2[slotL][i*96 + 64 + lane] = hvv2;
  }
}

// ---------------- decode: atoms + seq ----------------
__global__ __launch_bounds__(256) void decode_kernel(int buf,
    const float* __restrict__ rot, const float* __restrict__ trans,
    const float* __restrict__ Wp0, const float* __restrict__ Wt, const float* __restrict__ bt,
    const float* __restrict__ Wseq1, const float* __restrict__ bseq1,
    const float* __restrict__ Wseq2, const float* __restrict__ bseq2,
    const float* __restrict__ Wseq3, const float* __restrict__ bseq3,
    const float* __restrict__ lit_pos, const float* __restrict__ Wchi, const float* __restrict__ Wpsi,
    float* __restrict__ out)
{
  __shared__ float su[8][162];
  int lane = threadIdx.x & 31;
  int w = threadIdx.x >> 5;
  int i = blockIdx.x*8 + w;
  if (i >= NRES) return;

  float h0c = g_h0[buf][i*HDIM + lane];
  float t0 = 0.f;
  #pragma unroll
  for (int d = 0; d < 32; d++) t0 = fmaf(__shfl_sync(0xffffffffu, h0c, d), Wp0[d*32 + lane], t0);
  t0 = fmaxf(t0, 0.f);
  #pragma unroll
  for (int r = 0; r < 6; r++){
    int idx = r*32 + lane;
    int widx = idx < 162 ? idx : 161;
    float u = bt[widx];
    #pragma unroll
    for (int c = 0; c < 32; c++) u = fmaf(__shfl_sync(0xffffffffu, t0, c), Wt[c*162 + widx], u);
    if (idx < 162) su[w][idx] = u;
  }
  __syncwarp();
  for (int j = lane; j < 81; j += 32){
    float a = su[w][2*j], b = su[w][2*j+1];
    float ea = a + 1e-8f, eb = b + 1e-8f;
    float den = sqrtf(ea*ea + eb*eb);
    su[w][2*j]   = a / den;
    su[w][2*j+1] = b / den;
  }
  __syncwarp();
  float p0 = su[w][0], p1 = su[w][1];
  float r00=rot[i*9+0], r01=rot[i*9+1], r02=rot[i*9+2];
  float r10=rot[i*9+3], r11=rot[i*9+4], r12=rot[i*9+5];
  float r20=rot[i*9+6], r21=rot[i*9+7], r22=rot[i*9+8];

  for (int m = lane; m < 91; m += 32){
    int k, a;
    if (m < 4){ k = 0; a = m; }
    else { k = c_aa[m-4]; a = 4 + c_off[m-4]; }
    float chi[8];
    #pragma unroll
    for (int t = 0; t < 4; t++){
      chi[2*t]   = su[w][2*(1 + k*4 + t)];
      chi[2*t+1] = su[w][2*(1 + k*4 + t) + 1];
    }
    float l[3];
    #pragma unroll
    for (int j = 0; j < 3; j++){
      float acc = lit_pos[(k*14 + a)*3 + j];
      #pragma unroll
      for (int c = 0; c < 8; c++) acc = fmaf(chi[c], Wchi[(c*14 + a)*3 + j], acc);
      acc = fmaf(p0, Wpsi[(0*14 + a)*3 + j], acc);
      acc = fmaf(p1, Wpsi[(1*14 + a)*3 + j], acc);
      l[j] = acc;
    }
    out[((size_t)i*91 + m)*3 + 0] = r00*l[0] + r01*l[1] + r02*l[2];
    out[((size_t)i*91 + m)*3 + 1] = r10*l[0] + r11*l[1] + r12*l[2];
    out[((size_t)i*91 + m)*3 + 2] = r20*l[0] + r21*l[1] + r22*l[2];
  }

  float s1a = bseq1[lane], s1b = bseq1[32 + lane];
  #pragma unroll
  for (int d = 0; d < 32; d++){
    float h = __shfl_sync(0xffffffffu, h0c, d);
    s1a = fmaf(h, Wseq1[d*64 + lane],      s1a);
    s1b = fmaf(h, Wseq1[d*64 + 32 + lane], s1b);
  }
  s1a = fmaxf(s1a, 0.f); s1b = fmaxf(s1b, 0.f);
  float s2 = bseq2[lane];
  #pragma unroll
  for (int h = 0; h < 32; h++) s2 = fmaf(__shfl_sync(0xffffffffu, s1a, h), Wseq2[h*32 + lane], s2);
  #pragma unroll
  for (int h = 0; h < 32; h++) s2 = fmaf(__shfl_sync(0xffffffffu, s1b, h), Wseq2[(32+h)*32 + lane], s2);
  s2 = fmaxf(s2, 0.f);
  int ll = lane < 20 ? lane : 19;
  float lg = bseq3[ll];
  #pragma unroll
  for (int c = 0; c < 32; c++) lg = fmaf(__shfl_sync(0xffffffffu, s2, c), Wseq3[c*20 + ll], lg);
  float mv = (lane < 20) ? lg : -3.0e38f;
  #pragma unroll
  for (int o = 16; o > 0; o >>= 1) mv = fmaxf(mv, __shfl_xor_sync(0xffffffffu, mv, o));
  float ex = (lane < 20) ? expf(lg - mv) : 0.f;
  #pragma unroll
  for (int o = 16; o > 0; o >>= 1) ex += __shfl_xor_sync(0xffffffffu, ex, o);
  if (lane < 20) out[(size_t)NRES*273 + (size_t)i*20 + lane] = lg - mv - logf(ex);
}

// ---------------- launch ----------------
extern "C" void kernel_launch(void* const* d_in, const int* in_sizes, int n_in,
                              void* d_out, int out_size)
{
  const float* bb      = (const float*)d_in[0];
  const float* latent  = (const float*)d_in[1];
  const float* rrot    = (const float*)d_in[2];
  const float* rtrans  = (const float*)d_in[3];
  const float* Wemb0   = (const float*)d_in[4];
  const float* Wemb1   = (const float*)d_in[5];
  const float* We1s    = (const float*)d_in[6];
  const float* Wss     = (const float*)d_in[7];
  const float* Wds     = (const float*)d_in[8];
  const float* We2s    = (const float*)d_in[9];
  const float* Wvs     = (const float*)d_in[10];
  const float* W0s     = (const float*)d_in[11];
  const float* W1s     = (const float*)d_in[12];
  const float* Wu1s    = (const float*)d_in[13];
  const float* Wu2s    = (const float*)d_in[14];
  const float* Wp0     = (const float*)d_in[15];
  const float* Wt      = (const float*)d_in[16];
  const float* bt      = (const float*)d_in[17];
  const float* Wseq1   = (const float*)d_in[18];
  const float* bseq1   = (const float*)d_in[19];
  const float* Wseq2   = (const float*)d_in[20];
  const float* bseq2   = (const float*)d_in[21];
  const float* Wseq3   = (const float*)d_in[22];
  const float* bseq3   = (const float*)d_in[23];
  const float* lit_pos = (const float*)d_in[24];
  const float* Wchi    = (const float*)d_in[25];
  const float* Wpsi    = (const float*)d_in[26];
  const int*   bids    = (const int*)d_in[28];
  float* out = (float*)d_out;

  init_ranges_kernel<<<1, 32>>>();
  batch_range_kernel<<<(NRES+255)/256, 256>>>(bids);
  node_embed_kernel<<<1250, 256>>>(bb, latent, Wemb0, Wemb1,
                                   Wss, Wds, Wvs);           // layer-0 precompute
  knn_kernel<<<1250, 256>>>(bids);
  edge_init_kernel<<<(NEDGE+255)/256, 256>>>();

  // F0: phase1(0); epilogue -> ps0/pd0 slot0, hs1/hd1/hv1 slot1
  mp_first<<<1250, 256>>>(We1s, We2s, W0s, W1s, Wu1s,
                          Wss + 1024, Wds + 1024, Wvs + 1024);

  // G0 (l=0): bufIn=1, slotL=0; phase1(1); -> ps1/pd1 slot1, hs2/hd2/hv2 slot0
  mp_fused<false><<<1250, 256>>>(1, 0,
      Wu1s, Wu2s,
      We1s + 1024, We2s + 1024, W0s + 1024, W1s + 1024,
      Wu1s + 6144,
      Wss + 2048, Wds + 2048, Wvs + 2048);

  // G1 (l=1): bufIn=0, slotL=1; phase1(2); -> ps2/pd2 slot0, hs3/hd3/(hv3) slot1
  mp_fused<false><<<1250, 256>>>(0, 1,
      Wu1s + 6144, Wu2s + 2048,
      We1s + 2048, We2s + 2048, W0s + 2048, W1s + 2048,
      Wu1s + 2*6144,
      Wss + 3072, Wds + 3072, Wvs + 3072);

  // G2 (l=2): bufIn=1, slotL=0; phase1(3), LAST: no h1/ef/precompute writes
  mp_fused<true><<<1250, 256>>>(1, 0,
      Wu1s + 2*6144, Wu2s + 2*2048,
      We1s + 3072, We2s + 3072, W0s + 3072, W1s + 3072,
      Wu1s + 2*6144,
      Wss + 3072, Wds + 3072, Wvs + 3072);

  // final h0 in buffer 0
  decode_kernel<<<1250, 256>>>(0, rrot, rtrans, Wp0, Wt, bt,
                               Wseq1, bseq1, Wseq2, bseq2, Wseq3, bseq3,
                               lit_pos, Wchi, Wpsi, out);
}

// round 8
// speedup vs baseline: 1.2114x; 1.2114x over previous
#include <cuda_runtime.h>
#include <math.h>

#define NRES 10000
#define KNN 30
#define HDIM 32
#define NLAYERS 4
#define EFD 32
#define NEDGE (NRES*KNN)

// ---------------- device scratch ----------------
__device__ float g_h0[2][NRES*HDIM];
__device__ float g_h1[2][NRES*3*HDIM];
__device__ float g_ef[NEDGE*EFD];
__device__ int   g_src[NEDGE];
__device__ float4 g_xca4[NRES];           // (x,y,z,|x|^2)
__device__ int   g_bstart[8];
__device__ int   g_bend[8];
// per-node precomputes
__device__ float g_hs[NRES*HDIM];         // h0 @ Wss
__device__ float g_hd[NRES*HDIM];         // h0 @ Wds
__device__ float g_hv[NRES*3*HDIM];       // h1 @ Wvs
__device__ float g_ps[NRES*64];           // h0new @ Wu1[32:64]
__device__ float g_pd[NRES*64];           // h0new @ Wu1[64:96]

__constant__ int c_aa[87] = {
  0,
  1,1,1,1,1,1,1, 2,2,2,2, 3,3,3,3, 4,4, 5,5,5,5,5, 6,6,6,6,6,
  8,8,8,8,8,8, 9,9,9,9, 10,10,10,10, 11,11,11,11,11, 12,12,12,12,
  13,13,13,13,13,13,13, 14,14,14, 15,15, 16,16,16,
  17,17,17,17,17,17,17,17,17,17, 18,18,18,18,18,18,18,18, 19,19,19
};
__constant__ int c_off[87] = {
  0,
  0,1,2,3,4,5,6, 0,1,2,3, 0,1,2,3, 0,1, 0,1,2,3,4, 0,1,2,3,4,
  0,1,2,3,4,5, 0,1,2,3, 0,1,2,3, 0,1,2,3,4, 0,1,2,3,
  0,1,2,3,4,5,6, 0,1,2, 0,1, 0,1,2,
  0,1,2,3,4,5,6,7,8,9, 0,1,2,3,4,5,6,7, 0,1,2
};

__device__ __forceinline__ float fin0(float v){ return isfinite(v) ? v : 0.f; }

// ---------------- batch ranges ----------------
__global__ void init_ranges_kernel(){
  int t = threadIdx.x;
  if (t < 8){ g_bstart[t] = NRES; g_bend[t] = 0; }
}
__global__ void batch_range_kernel(const int* __restrict__ bid){
  int i = blockIdx.x*blockDim.x + threadIdx.x;
  if (i >= NRES) return;
  int b = bid[i];
  atomicMin(&g_bstart[b], i);
  atomicMax(&g_bend[b], i+1);
}

// ---------------- node features + embeddings (warp per node, lane=channel) ----------------
__global__ __launch_bounds__(256) void node_embed_kernel(
    const float* __restrict__ bb, const float* __restrict__ lat,
    const float* __restrict__ Wemb0, const float* __restrict__ Wemb1)
{
  int lane = threadIdx.x & 31;
  int i = blockIdx.x*8 + (threadIdx.x >> 5);
  if (i >= NRES) return;

  float ca0 = bb[i*12+3], ca1 = bb[i*12+4], ca2 = bb[i*12+5];
  if (lane == 0){
    g_xca4[i] = make_float4(ca0, ca1, ca2, ca0*ca0 + ca1*ca1 + ca2*ca2);
  }

  float Dv[3];
  #pragma unroll
  for (int t3 = 0; t3 < 3; t3++){
    int t = 3*i + t3;
    float D = 0.f;
    if (t >= 1 && t <= 3*NRES - 3){
      int d0 = t - 1;
      float x[4][3];
      #pragma unroll
      for (int q = 0; q < 4; q++){
        int m = d0 + q; int r = m/3; int am = m - r*3;
        x[q][0] = bb[r*12 + am*3 + 0];
        x[q][1] = bb[r*12 + am*3 + 1];
        x[q][2] = bb[r*12 + am*3 + 2];
      }
      float u2[3], u1[3], u0[3];
      #pragma unroll
      for (int c = 0; c < 3; c++){ u2[c]=x[1][c]-x[0][c]; u1[c]=x[2][c]-x[1][c]; u0[c]=x[3][c]-x[2][c]; }
      float n2n = sqrtf(u2[0]*u2[0]+u2[1]*u2[1]+u2[2]*u2[2]) + 1e-8f;
      float n1n = sqrtf(u1[0]*u1[0]+u1[1]*u1[1]+u1[2]*u1[2]) + 1e-8f;
      float n0n = sqrtf(u0[0]*u0[0]+u0[1]*u0[1]+u0[2]*u0[2]) + 1e-8f;
      #pragma unroll
      for (int c = 0; c < 3; c++){ u2[c]/=n2n; u1[c]/=n1n; u0[c]/=n0n; }
      float c21[3] = { u2[1]*u1[2]-u2[2]*u1[1], u2[2]*u1[0]-u2[0]*u1[2], u2[0]*u1[1]-u2[1]*u1[0] };
      float c10[3] = { u1[1]*u0[2]-u1[2]*u0[1], u1[2]*u0[0]-u1[0]*u0[2], u1[0]*u0[1]-u1[1]*u0[0] };
      float l21 = sqrtf(c21[0]*c21[0]+c21[1]*c21[1]+c21[2]*c21[2]) + 1e-8f;
      float l10 = sqrtf(c10[0]*c10[0]+c10[1]*c10[1]+c10[2]*c10[2]) + 1e-8f;
      #pragma unroll
      for (int c = 0; c < 3; c++){ c21[c]/=l21; c10[c]/=l10; }
      float cosD = c21[0]*c10[0]+c21[1]*c10[1]+c21[2]*c10[2];
      cosD = fminf(fmaxf(cosD, -1.f + 1e-7f), 1.f - 1e-7f);
      float sdot = u2[0]*c10[0]+u2[1]*c10[1]+u2[2]*c10[2];
      float sgn = (sdot > 0.f) ? 1.f : ((sdot < 0.f) ? -1.f : 0.f);
      D = sgn * acosf(cosD);
    }
    Dv[t3] = D;
  }
  float x0[7] = { cosf(Dv[0]), cosf(Dv[1]), cosf(Dv[2]),
                  sinf(Dv[0]), sinf(Dv[1]), sinf(Dv[2]), 1.f };

  float v[7][3];
  #pragma unroll
  for (int a = 0; a < 4; a++){
    v[a][0] = bb[i*12 + a*3 + 0] - ca0;
    v[a][1] = bb[i*12 + a*3 + 1] - ca1;
    v[a][2] = bb[i*12 + a*3 + 2] - ca2;
  }
  if (i < NRES-1){
    float dx = bb[(i+1)*12+3] - ca0, dy = bb[(i+1)*12+4] - ca1, dz = bb[(i+1)*12+5] - ca2;
    float n = sqrtf(dx*dx+dy*dy+dz*dz) + 1e-8f;
    v[4][0]=dx/n; v[4][1]=dy/n; v[4][2]=dz/n;
  } else { v[4][0]=v[4][1]=v[4][2]=0.f; }
  if (i > 0){
    float dx = ca0 - bb[(i-1)*12+3], dy = ca1 - bb[(i-1)*12+4], dz = ca2 - bb[(i-1)*12+5];
    float n = sqrtf(dx*dx+dy*dy+dz*dz) + 1e-8f;
    v[5][0]=-dx/n; v[5][1]=-dy/n; v[5][2]=-dz/n;
  } else { v[5][0]=v[5][1]=v[5][2]=0.f; }
  {
    float b0 = ca0 - bb[i*12+0], b1 = ca1 - bb[i*12+1], b2 = ca2 - bb[i*12+2];
    float cc0 = bb[i*12+6] - ca0, cc1 = bb[i*12+7] - ca1, cc2 = bb[i*12+8] - ca2;
    float a0 = b1*cc2 - b2*cc1, a1 = b2*cc0 - b0*cc2, a2 = b0*cc1 - b1*cc0;
    v[6][0] = -0.58273431f*a0 + 0.56802827f*b0 - 0.54067466f*cc0;
    v[6][1] = -0.58273431f*a1 + 0.56802827f*b1 - 0.54067466f*cc1;
    v[6][2] = -0.58273431f*a2 + 0.56802827f*b2 - 0.54067466f*cc2;
  }
  #pragma unroll
  for (int q = 0; q < 7; q++){
    v[q][0]=fin0(v[q][0]); v[q][1]=fin0(v[q][1]); v[q][2]=fin0(v[q][2]);
  }

  float acc = 0.f;
  #pragma unroll
  for (int d = 0; d < 7; d++) acc = fmaf(x0[d], Wemb0[d*32 + lane], acc);
  for (int d = 0; d < 32; d++) acc = fmaf(lat[(i*4+0)*32 + d], Wemb0[(7+d)*32 + lane], acc);
  g_h0[0][i*32 + lane] = fmaxf(acc, 0.f);

  #pragma unroll
  for (int j = 0; j < 3; j++){
    float a2 = 0.f;
    #pragma unroll
    for (int d = 0; d < 7; d++) a2 = fmaf(v[d][j], Wemb1[d*32 + lane], a2);
    for (int d = 0; d < 32; d++) a2 = fmaf(lat[(i*4+1+j)*32 + d], Wemb1[(7+d)*32 + lane], a2);
    g_h1[0][(i*3+j)*32 + lane] = a2;
  }
}

// ---------------- kNN: one WARP per row, register-only bitonic top-32 ----------------
__device__ __forceinline__ unsigned long long shfx64(unsigned long long v, int m){
  return __shfl_xor_sync(0xffffffffu, v, m);
}

__global__ __launch_bounds__(256) void knn_kernel(const int* __restrict__ bid){
  int lane = threadIdx.x & 31;
  int i = blockIdx.x*8 + (threadIdx.x >> 5);
  if (i >= NRES) return;
  float4 qi = g_xca4[i];
  int b = bid[i];
  int lo = g_bstart[b], hi = g_bend[b];

  const unsigned long long INF = 0xFFFFFFFFFFFFFFFFull;
  unsigned long long state = INF;
  unsigned long long worst = INF;

  for (int j0 = lo; j0 < hi; j0 += 32){
    int j = j0 + lane;
    unsigned long long key = INF;
    if (j < hi && j != i){
      float4 qj = g_xca4[j];
      float d2 = fmaf(-2.f, qi.x*qj.x + qi.y*qj.y + qi.z*qj.z, qi.w + qj.w);
      unsigned int fb = __float_as_uint(d2);
      fb = (fb & 0x80000000u) ? ~fb : (fb | 0x80000000u);
      key = ((unsigned long long)fb << 32) | (unsigned int)j;
    }
    if (!__any_sync(0xffffffffu, key < worst)) continue;

    #pragma unroll
    for (int k = 2; k <= 32; k <<= 1){
      #pragma unroll
      for (int jj = k >> 1; jj > 0; jj >>= 1){
        unsigned long long o = shfx64(key, jj);
        bool up = ((lane & k) == 0);
        bool lower = ((lane & jj) == 0);
        bool keepmin = (up == lower);
        key = ((o < key) == keepmin) ? o : key;
      }
    }
    unsigned long long rev = shfx64(key, 31);
    unsigned long long m = (rev < state) ? rev : state;
    #pragma unroll
    for (int jj = 16; jj > 0; jj >>= 1){
      unsigned long long o = shfx64(m, jj);
      bool lower = ((lane & jj) == 0);
      m = ((o < m) == lower) ? o : m;
    }
    state = m;
    worst = __shfl_sync(0xffffffffu, state, 31);
  }

  if (lane < KNN){
    g_src[i*KNN + lane] = (state == INF) ? i : (int)(unsigned int)(state & 0xFFFFFFFFull);
  }
}

// ---------------- edge init ----------------
__global__ void edge_init_kernel(){
  int e = blockIdx.x*blockDim.x + threadIdx.x;
  if (e >= NEDGE) return;
  int i = e / KNN;
  int s = g_src[e];
  float4 qi = g_xca4[i], qs = g_xca4[s];
  float vx = qi.x - qs.x, vy = qi.y - qs.y, vz = qi.z - qs.z;
  float dist = sqrtf(vx*vx + vy*vy + vz*vz);
  float* ef = &g_ef[e*EFD];
  #pragma unroll
  for (int j = 0; j < 16; j++){
    float mu = (float)j * (20.f/15.f);
    float t = (dist - mu) / 1.25f;
    ef[j] = expf(-t*t);
  }
  float diff = (float)(s - i);
  #pragma unroll
  for (int f = 0; f < 8; f++){
    float fr = expf(-((float)(2*f)/16.f) * 9.210340371976184f);
    float a = diff * fr;
    ef[16+f] = cosf(a);
    ef[24+f] = sinf(a);
  }
}

// ---------------- per-node precompute: hs, hd, (hv) ----------------
template<bool DOHV>
__global__ __launch_bounds__(256) void precompA_kernel(int buf,
    const float* __restrict__ Wss, const float* __restrict__ Wds, const float* __restrict__ Wvs)
{
  __shared__ float sWss[1024], sWds[1024], sWvs[1024];
  for (int t = threadIdx.x; t < 1024; t += 256){
    sWss[t]=Wss[t]; sWds[t]=Wds[t];
    if (DOHV) sWvs[t]=Wvs[t];
  }
  __syncthreads();
  int lane = threadIdx.x & 31;
  int i = blockIdx.x*8 + (threadIdx.x >> 5);
  if (i >= NRES) return;
  float h0 = g_h0[buf][i*32 + lane];
  float hs0 = 0.f, hs1 = 0.f, hd0 = 0.f, hd1 = 0.f;
  #pragma unroll
  for (int d = 0; d < 32; d += 2){
    float a = __shfl_sync(0xffffffffu, h0, d);
    float b = __shfl_sync(0xffffffffu, h0, d+1);
    hs0 = fmaf(a, sWss[d*32+lane], hs0);     hs1 = fmaf(b, sWss[(d+1)*32+lane], hs1);
    hd0 = fmaf(a, sWds[d*32+lane], hd0);     hd1 = fmaf(b, sWds[(d+1)*32+lane], hd1);
  }
  g_hs[i*32+lane] = hs0 + hs1;
  g_hd[i*32+lane] = hd0 + hd1;
  if (DOHV){
    #pragma unroll
    for (int c = 0; c < 3; c++){
      float h1 = g_h1[buf][(i*3+c)*32 + lane];
      float a0 = 0.f, a1 = 0.f;
      #pragma unroll
      for (int d = 0; d < 32; d += 2){
        a0 = fmaf(__shfl_sync(0xffffffffu, h1, d),   sWvs[d*32+lane],     a0);
        a1 = fmaf(__shfl_sync(0xffffffffu, h1, d+1), sWvs[(d+1)*32+lane], a1);
      }
      g_hv[i*96 + c*32 + lane] = a0 + a1;
    }
  }
}

// ---------------- phase 1: chunked two-phase GEMV ----------------
#define CHK 10
template<bool LAST>
__global__ __launch_bounds__(256) void mp_phase1(int bufIn,
    const float* __restrict__ We1, const float* __restrict__ We2,
    const float* __restrict__ W0,  const float* __restrict__ W1,
    const float* __restrict__ Wu1)
{
  __shared__ __align__(16) float sWe1T[1024];  // [c][d]
  __shared__ __align__(16) float sWe2T[1024];  // [c][d]
  __shared__ __align__(16) float sE[8][CHK][32];
  __shared__ __align__(16) float sT[8][CHK][32];
  __shared__ int sSrc[8][32];

  for (int t = threadIdx.x; t < 1024; t += 256){
    sWe1T[t] = We1[(t&31)*32 + (t>>5)];
    sWe2T[t] = We2[(t&31)*32 + (t>>5)];
  }
  __syncthreads();

  const float* h0in = g_h0[bufIn];  float* h0out = g_h0[bufIn^1];
  const float* h1in = g_h1[bufIn];  float* h1out = g_h1[bufIn^1];
  int lane = threadIdx.x & 31;
  int w = threadIdx.x >> 5;
  int i = blockIdx.x*8 + w;
  if (i >= NRES) return;

  if (lane < KNN) sSrc[w][lane] = g_src[i*KNN + lane];
  __syncwarp();

  float h0d = h0in[i*HDIM + lane];
  float hd  = g_hd[i*HDIM + lane];
  float acc0 = 0.f, av0 = 0.f, av1 = 0.f, av2 = 0.f;

  for (int c0 = 0; c0 < KNN; c0 += CHK){
    #pragma unroll
    for (int k = 0; k < CHK; k++)
      sE[w][k][lane] = g_ef[((size_t)(i*KNN + c0 + k))*EFD + lane];
    __syncwarp();
    #pragma unroll
    for (int k = 0; k < CHK; k++){
      int s = sSrc[w][c0 + k];
      float t0 = hd + g_hs[s*HDIM + lane];
      float t1 = 0.f;
      #pragma unroll
      for (int d4 = 0; d4 < 8; d4++){
        float4 a  = *(const float4*)&sE[w][k][d4*4];
        float4 wv = *(const float4*)&sWe1T[lane*32 + d4*4];
        t0 = fmaf(a.x, wv.x, t0); t1 = fmaf(a.y, wv.y, t1);
        t0 = fmaf(a.z, wv.z, t0); t1 = fmaf(a.w, wv.w, t1);
      }
      sT[w][k][lane] = fmaxf(t0 + t1, 0.f);
    }
    __syncwarp();
    #pragma unroll
    for (int k = 0; k < CHK; k++){
      int s = sSrc[w][c0 + k];
      float g0 = 0.f, g1 = 0.f;
      #pragma unroll
      for (int d4 = 0; d4 < 8; d4++){
        float4 a  = *(const float4*)&sT[w][k][d4*4];
        float4 wv = *(const float4*)&sWe2T[lane*32 + d4*4];
        g0 = fmaf(a.x, wv.x, g0); g1 = fmaf(a.y, wv.y, g1);
        g0 = fmaf(a.z, wv.z, g0); g1 = fmaf(a.w, wv.w, g1);
      }
      float g = g0 + g1;
      acc0 = fmaf(g, h0in[s*HDIM + lane], acc0);
      if (!LAST){
        const float* hv = &g_hv[s*96];
        av0 = fmaf(g, hv[lane],    av0);
        av1 = fmaf(g, hv[32+lane], av1);
        av2 = fmaf(g, hv[64+lane], av2);
      }
    }
    __syncwarp();
  }

  const float inv = 1.f/(float)KNN;
  acc0 *= inv;

  // h0 update (weights via __ldg; once per node)
  float u0 = 0.f, u1 = 0.f;
  #pragma unroll
  for (int d = 0; d < 32; d += 2){
    u0 = fmaf(__shfl_sync(0xffffffffu, acc0, d),   __ldg(&W0[d*32+lane]),     u0);
    u1 = fmaf(__shfl_sync(0xffffffffu, acc0, d+1), __ldg(&W0[(d+1)*32+lane]), u1);
  }
  float h0new = h0d + fmaxf(u0 + u1, 0.f);
  h0out[i*HDIM + lane] = h0new;

  if (!LAST){
    av0 *= inv; av1 *= inv; av2 *= inv;
    // h1 update
    float o0 = 0.f, o1 = 0.f, o2 = 0.f;
    #pragma unroll
    for (int d = 0; d < 32; d++){
      float wv = __ldg(&W1[d*32+lane]);
      o0 = fmaf(__shfl_sync(0xffffffffu, av0, d), wv, o0);
      o1 = fmaf(__shfl_sync(0xffffffffu, av1, d), wv, o1);
      o2 = fmaf(__shfl_sync(0xffffffffu, av2, d), wv, o2);
    }
    h1out[(i*3+0)*HDIM + lane] = h1in[(i*3+0)*HDIM + lane] + o0;
    h1out[(i*3+1)*HDIM + lane] = h1in[(i*3+1)*HDIM + lane] + o1;
    h1out[(i*3+2)*HDIM + lane] = h1in[(i*3+2)*HDIM + lane] + o2;

    // fused phase-2 precompute from h0new
    const float* U1b = Wu1 + 2048;
    const float* U1c = Wu1 + 4096;
    float psa = 0.f, psb = 0.f, pda = 0.f, pdb = 0.f;
    #pragma unroll
    for (int d = 0; d < 32; d++){
      float h = __shfl_sync(0xffffffffu, h0new, d);
      psa = fmaf(h, __ldg(&U1b[d*64 + lane]),      psa);
      psb = fmaf(h, __ldg(&U1b[d*64 + 32 + lane]), psb);
      pda = fmaf(h, __ldg(&U1c[d*64 + lane]),      pda);
      pdb = fmaf(h, __ldg(&U1c[d*64 + 32 + lane]), pdb);
    }
    g_ps[i*64 + lane]      = psa;
    g_ps[i*64 + 32 + lane] = psb;
    g_pd[i*64 + lane]      = pda;
    g_pd[i*64 + 32 + lane] = pdb;
  }
}

// ---------------- phase 2: ef update, chunked two-phase ----------------
__global__ __launch_bounds__(256) void mp_phase2(const float* __restrict__ Wu1,
                                                 const float* __restrict__ Wu2)
{
  __shared__ __align__(16) float sU1aT[2048];   // [c][d], c in 0..63
  __shared__ __align__(16) float sW2T[2048];    // [c][h], c in 0..31, h in 0..63
  __shared__ __align__(16) float sE[8][CHK][32];
  __shared__ __align__(16) float sY[8][CHK][64];
  __shared__ int sSrc[8][32];

  for (int t = threadIdx.x; t < 2048; t += 256){
    sU1aT[t] = Wu1[(t&31)*64 + (t>>5)];
    sW2T[t]  = Wu2[(t&63)*32 + (t>>6)];
  }
  __syncthreads();

  int lane = threadIdx.x & 31;
  int w = threadIdx.x >> 5;
  int i = blockIdx.x*8 + w;
  if (i >= NRES) return;

  if (lane < KNN) sSrc[w][lane] = g_src[i*KNN + lane];
  __syncwarp();

  float pda = g_pd[i*64 + lane];
  float pdb = g_pd[i*64 + 32 + lane];

  for (int c0 = 0; c0 < KNN; c0 += CHK){
    #pragma unroll
    for (int k = 0; k < CHK; k++)
      sE[w][k][lane] = g_ef[((size_t)(i*KNN + c0 + k))*EFD + lane];
    __syncwarp();
    #pragma unroll
    for (int k = 0; k < CHK; k++){
      int s = sSrc[w][c0 + k];
      float y0 = pda + g_ps[s*64 + lane];
      float y1 = pdb + g_ps[s*64 + 32 + lane];
      #pragma unroll
      for (int d4 = 0; d4 < 8; d4++){
        float4 a  = *(const float4*)&sE[w][k][d4*4];
        float4 w0 = *(const float4*)&sU1aT[lane*32 + d4*4];
        float4 w1 = *(const float4*)&sU1aT[(lane+32)*32 + d4*4];
        y0 = fmaf(a.x, w0.x, y0); y0 = fmaf(a.y, w0.y, y0);
        y0 = fmaf(a.z, w0.z, y0); y0 = fmaf(a.w, w0.w, y0);
        y1 = fmaf(a.x, w1.x, y1); y1 = fmaf(a.y, w1.y, y1);
        y1 = fmaf(a.z, w1.z, y1); y1 = fmaf(a.w, w1.w, y1);
      }
      sY[w][k][lane]      = fmaxf(y0, 0.f);
      sY[w][k][32 + lane] = fmaxf(y1, 0.f);
    }
    __syncwarp();
    #pragma unroll
    for (int k = 0; k < CHK; k++){
      float oA = 0.f, oB = 0.f;
      #pragma unroll
      for (int h4 = 0; h4 < 16; h4++){
        float4 a  = *(const float4*)&sY[w][k][h4*4];
        float4 wv = *(const float4*)&sW2T[lane*64 + h4*4];
        oA = fmaf(a.x, wv.x, oA); oB = fmaf(a.y, wv.y, oB);
        oA = fmaf(a.z, wv.z, oA); oB = fmaf(a.w, wv.w, oB);
      }
      g_ef[((size_t)(i*KNN + c0 + k))*EFD + lane] = sE[w][k][lane] + oA + oB;
    }
    __syncwarp();
  }
}

// ---------------- decode: atoms + seq ----------------
__global__ __launch_bounds__(256) void decode_kernel(int buf,
    const float* __restrict__ rot, const float* __restrict__ trans,
    const float* __restrict__ Wp0, const float* __restrict__ Wt, const float* __restrict__ bt,
    const float* __restrict__ Wseq1, const float* __restrict__ bseq1,
    const float* __restrict__ Wseq2, const float* __restrict__ bseq2,
    const float* __restrict__ Wseq3, const float* __restrict__ bseq3,
    const float* __restrict__ lit_pos, const float* __restrict__ Wchi, const float* __restrict__ Wpsi,
    float* __restrict__ out)
{
  __shared__ float su[8][162];
  int lane = threadIdx.x & 31;
  int w = threadIdx.x >> 5;
  int i = blockIdx.x*8 + w;
  if (i >= NRES) return;

  float h0c = g_h0[buf][i*HDIM + lane];
  float t0 = 0.f;
  #pragma unroll
  for (int d = 0; d < 32; d++) t0 = fmaf(__shfl_sync(0xffffffffu, h0c, d), Wp0[d*32 + lane], t0);
  t0 = fmaxf(t0, 0.f);
  #pragma unroll
  for (int r = 0; r < 6; r++){
    int idx = r*32 + lane;
    int widx = idx < 162 ? idx : 161;
    float u = bt[widx];
    #pragma unroll
    for (int c = 0; c < 32; c++) u = fmaf(__shfl_sync(0xffffffffu, t0, c), Wt[c*162 + widx], u);
    if (idx < 162) su[w][idx] = u;
  }
  __syncwarp();
  for (int j = lane; j < 81; j += 32){
    float a = su[w][2*j], b = su[w][2*j+1];
    float ea = a + 1e-8f, eb = b + 1e-8f;
    float den = sqrtf(ea*ea + eb*eb);
    su[w][2*j]   = a / den;
    su[w][2*j+1] = b / den;
  }
  __syncwarp();
  float p0 = su[w][0], p1 = su[w][1];
  float r00=rot[i*9+0], r01=rot[i*9+1], r02=rot[i*9+2];
  float r10=rot[i*9+3], r11=rot[i*9+4], r12=rot[i*9+5];
  float r20=rot[i*9+6], r21=rot[i*9+7], r22=rot[i*9+8];

  for (int m = lane; m < 91; m += 32){
    int k, a;
    if (m < 4){ k = 0; a = m; }
    else { k = c_aa[m-4]; a = 4 + c_off[m-4]; }
    float chi[8];
    #pragma unroll
    for (int t = 0; t < 4; t++){
      chi[2*t]   = su[w][2*(1 + k*4 + t)];
      chi[2*t+1] = su[w][2*(1 + k*4 + t) + 1];
    }
    float l[3];
    #pragma unroll
    for (int j = 0; j < 3; j++){
      float acc = lit_pos[(k*14 + a)*3 + j];
      #pragma unroll
      for (int c = 0; c < 8; c++) acc = fmaf(chi[c], Wchi[(c*14 + a)*3 + j], acc);
      acc = fmaf(p0, Wpsi[(0*14 + a)*3 + j], acc);
      acc = fmaf(p1, Wpsi[(1*14 + a)*3 + j], acc);
      l[j] = acc;
    }
    out[((size_t)i*91 + m)*3 + 0] = r00*l[0] + r01*l[1] + r02*l[2];
    out[((size_t)i*91 + m)*3 + 1] = r10*l[0] + r11*l[1] + r12*l[2];
    out[((size_t)i*91 + m)*3 + 2] = r20*l[0] + r21*l[1] + r22*l[2];
  }

  float s1a = bseq1[lane], s1b = bseq1[32 + lane];
  #pragma unroll
  for (int d = 0; d < 32; d++){
    float h = __shfl_sync(0xffffffffu, h0c, d);
    s1a = fmaf(h, Wseq1[d*64 + lane],      s1a);
    s1b = fmaf(h, Wseq1[d*64 + 32 + lane], s1b);
  }
  s1a = fmaxf(s1a, 0.f); s1b = fmaxf(s1b, 0.f);
  float s2 = bseq2[lane];
  #pragma unroll
  for (int h = 0; h < 32; h++) s2 = fmaf(__shfl_sync(0xffffffffu, s1a, h), Wseq2[h*32 + lane], s2);
  #pragma unroll
  for (int h = 0; h < 32; h++) s2 = fmaf(__shfl_sync(0xffffffffu, s1b, h), Wseq2[(32+h)*32 + lane], s2);
  s2 = fmaxf(s2, 0.f);
  int ll = lane < 20 ? lane : 19;
  float lg = bseq3[ll];
  #pragma unroll
  for (int c = 0; c < 32; c++) lg = fmaf(__shfl_sync(0xffffffffu, s2, c), Wseq3[c*20 + ll], lg);
  float mv = (lane < 20) ? lg : -3.0e38f;
  #pragma unroll
  for (int o = 16; o > 0; o >>= 1) mv = fmaxf(mv, __shfl_xor_sync(0xffffffffu, mv, o));
  float ex = (lane < 20) ? expf(lg - mv) : 0.f;
  #pragma unroll
  for (int o = 16; o > 0; o >>= 1) ex += __shfl_xor_sync(0xffffffffu, ex, o);
  if (lane < 20) out[(size_t)NRES*273 + (size_t)i*20 + lane] = lg - mv - logf(ex);
}

// ---------------- launch ----------------
extern "C" void kernel_launch(void* const* d_in, const int* in_sizes, int n_in,
                              void* d_out, int out_size)
{
  const float* bb      = (const float*)d_in[0];
  const float* latent  = (const float*)d_in[1];
  const float* rrot    = (const float*)d_in[2];
  const float* rtrans  = (const float*)d_in[3];
  const float* Wemb0   = (const float*)d_in[4];
  const float* Wemb1   = (const float*)d_in[5];
  const float* We1s    = (const float*)d_in[6];
  const float* Wss     = (const float*)d_in[7];
  const float* Wds     = (const float*)d_in[8];
  const float* We2s    = (const float*)d_in[9];
  const float* Wvs     = (const float*)d_in[10];
  const float* W0s     = (const float*)d_in[11];
  const float* W1s     = (const float*)d_in[12];
  const float* Wu1s    = (const float*)d_in[13];
  const float* Wu2s    = (const float*)d_in[14];
  const float* Wp0     = (const float*)d_in[15];
  const float* Wt      = (const float*)d_in[16];
  const float* bt      = (const float*)d_in[17];
  const float* Wseq1   = (const float*)d_in[18];
  const float* bseq1   = (const float*)d_in[19];
  const float* Wseq2   = (const float*)d_in[20];
  const float* bseq2   = (const float*)d_in[21];
  const float* Wseq3   = (const float*)d_in[22];
  const float* bseq3   = (const float*)d_in[23];
  const float* lit_pos = (const float*)d_in[24];
  const float* Wchi    = (const float*)d_in[25];
  const float* Wpsi    = (const float*)d_in[26];
  const int*   bids    = (const int*)d_in[28];
  float* out = (float*)d_out;

  init_ranges_kernel<<<1, 32>>>();
  batch_range_kernel<<<(NRES+255)/256, 256>>>(bids);
  node_embed_kernel<<<1250, 256>>>(bb, latent, Wemb0, Wemb1);
  knn_kernel<<<1250, 256>>>(bids);
  edge_init_kernel<<<(NEDGE+255)/256, 256>>>();

  int cur = 0;
  for (int l = 0; l < 3; l++){
    precompA_kernel<true><<<1250, 256>>>(cur,
        Wss + l*HDIM*HDIM, Wds + l*HDIM*HDIM, Wvs + l*HDIM*HDIM);
    mp_phase1<false><<<1250, 256>>>(cur,
        We1s + l*EFD*HDIM, We2s + l*HDIM*HDIM,
        W0s + l*HDIM*HDIM, W1s + l*HDIM*HDIM,
        Wu1s + l*96*64);
    mp_phase2<<<1250, 256>>>(Wu1s + l*96*64, Wu2s + l*64*32);
    cur ^= 1;
  }
  // layer 3: no hv, no phase2, slim phase1 (h0 only)
  precompA_kernel<false><<<1250, 256>>>(cur,
      Wss + 3*HDIM*HDIM, Wds + 3*HDIM*HDIM, Wvs + 3*HDIM*HDIM);
  mp_phase1<true><<<1250, 256>>>(cur,
      We1s + 3*EFD*HDIM, We2s + 3*HDIM*HDIM,
      W0s + 3*HDIM*HDIM, W1s + 3*HDIM*HDIM,
      Wu1s + 3*96*64);
  cur ^= 1;

  decode_kernel<<<1250, 256>>>(cur, rrot, rtrans, Wp0, Wt, bt,
                               Wseq1, bseq1, Wseq2, bseq2, Wseq3, bseq3,
                               lit_pos, Wchi, Wpsi, out);
}